// round 2
// baseline (speedup 1.0000x reference)
#include <cuda_runtime.h>

#define D_MODEL 1024
#define NH      16
#define DK      64
#define BATCH   2
#define SEQ     2048
#define MTOK    (BATCH*SEQ)     // 4096
#define QKV_N   (3*D_MODEL)     // 3072

// Scratch (alloc-free rule: __device__ globals)
__device__ float g_qkv[(size_t)MTOK * QKV_N];   // [4096, 3072]
__device__ float g_att[(size_t)MTOK * D_MODEL]; // [4096, 1024]

// ---------------------------------------------------------------------------
// GEMM: C[M,N] = A[M,K] @ B[N,K]^T + bias[N]   (both operands K-major)
// 128x128 tile, K-step 8, 256 threads, 8x8 per-thread register block.
// ---------------------------------------------------------------------------
#define GTM 128
#define GTN 128
#define GTK 8

__global__ __launch_bounds__(256) void sgemm_nt_bias(
    const float* __restrict__ A, const float* __restrict__ Bm,
    const float* __restrict__ bias, float* __restrict__ C,
    int M, int N, int K)
{
    __shared__ float As[GTK][GTM];
    __shared__ float Bs[GTK][GTN];

    const int tid = threadIdx.x;
    const int tx  = tid & 15;        // 0..15 -> N dimension
    const int ty  = tid >> 4;        // 0..15 -> M dimension
    const int row0 = blockIdx.y * GTM;
    const int col0 = blockIdx.x * GTN;

    float acc[8][8];
#pragma unroll
    for (int i = 0; i < 8; i++)
#pragma unroll
        for (int j = 0; j < 8; j++) acc[i][j] = 0.f;

    // tile loading: each thread loads one float4 of A and one of B per k-step
    const int lrow = tid >> 1;        // 0..127
    const int lk4  = (tid & 1) * 4;   // 0 or 4
    const float* Ap = A  + (size_t)(row0 + lrow) * K + lk4;
    const float* Bp = Bm + (size_t)(col0 + lrow) * K + lk4;

    for (int k0 = 0; k0 < K; k0 += GTK) {
        float4 av = *(const float4*)(Ap + k0);
        float4 bv = *(const float4*)(Bp + k0);
        As[lk4 + 0][lrow] = av.x; As[lk4 + 1][lrow] = av.y;
        As[lk4 + 2][lrow] = av.z; As[lk4 + 3][lrow] = av.w;
        Bs[lk4 + 0][lrow] = bv.x; Bs[lk4 + 1][lrow] = bv.y;
        Bs[lk4 + 2][lrow] = bv.z; Bs[lk4 + 3][lrow] = bv.w;
        __syncthreads();

#pragma unroll
        for (int kk = 0; kk < GTK; kk++) {
            float4 a0 = *(const float4*)&As[kk][ty * 8];
            float4 a1 = *(const float4*)&As[kk][ty * 8 + 4];
            float4 b0 = *(const float4*)&Bs[kk][tx * 8];
            float4 b1 = *(const float4*)&Bs[kk][tx * 8 + 4];
            float a[8] = {a0.x, a0.y, a0.z, a0.w, a1.x, a1.y, a1.z, a1.w};
            float b[8] = {b0.x, b0.y, b0.z, b0.w, b1.x, b1.y, b1.z, b1.w};
#pragma unroll
            for (int i = 0; i < 8; i++)
#pragma unroll
                for (int j = 0; j < 8; j++)
                    acc[i][j] += a[i] * b[j];
        }
        __syncthreads();
    }

    float bi[8];
#pragma unroll
    for (int j = 0; j < 8; j++) bi[j] = bias[col0 + tx * 8 + j];

#pragma unroll
    for (int i = 0; i < 8; i++) {
        size_t r = (size_t)(row0 + ty * 8 + i);
        int c = col0 + tx * 8;
#pragma unroll
        for (int j = 0; j < 8; j++)
            C[r * N + c + j] = acc[i][j] + bi[j];
    }
}

// ---------------------------------------------------------------------------
// Flash attention (causal), fp32. One block = 64 queries of one (b, h).
// 256 threads = 16x16; thread owns 4x4 of S-tile and 4x4 of O (over dk).
// P@V uses register P broadcast via shfl (width 16) -> no P smem buffer.
// ---------------------------------------------------------------------------
#define BQ  64
#define BKT 64
#define KS_STRIDE (DK + 1)
#define ATT_SMEM ((BQ*DK + BKT*KS_STRIDE + BKT*DK) * (int)sizeof(float))  // 49408

__global__ __launch_bounds__(256) void flash_attn(
    const float* __restrict__ qkv, float* __restrict__ att)
{
    extern __shared__ float sm[];
    float* Qs = sm;                       // [64][64]
    float* Ks = Qs + BQ * DK;             // [64][65] padded
    float* Vs = Ks + BKT * KS_STRIDE;     // [64][64]

    const int qt  = blockIdx.x;           // query tile 0..31
    const int h   = blockIdx.y;
    const int b   = blockIdx.z;
    const int tid = threadIdx.x;
    const int tx  = tid & 15;
    const int ty  = tid >> 4;
    const int r0  = ty * 4;               // query rows within tile
    const int c0  = tx * 4;               // key cols (S) / d cols (O)
    const int q0  = qt * BQ;

    const float* base = qkv + (size_t)b * SEQ * QKV_N + h * DK;

    // Load Q tile (64x64), coalesced float4
    for (int i = tid; i < BQ * DK / 4; i += 256) {
        int r  = i >> 4;
        int d4 = (i & 15) << 2;
        float4 v = *(const float4*)(base + (size_t)(q0 + r) * QKV_N + d4);
        Qs[r * DK + d4 + 0] = v.x; Qs[r * DK + d4 + 1] = v.y;
        Qs[r * DK + d4 + 2] = v.z; Qs[r * DK + d4 + 3] = v.w;
    }

    float m_i[4], l_i[4], o[4][4];
#pragma unroll
    for (int i = 0; i < 4; i++) {
        m_i[i] = -1e30f; l_i[i] = 0.f;
#pragma unroll
        for (int j = 0; j < 4; j++) o[i][j] = 0.f;
    }

    for (int kt = 0; kt <= qt; kt++) {
        const int k0 = kt * BKT;
        // Load K and V tiles
        for (int i = tid; i < BKT * DK / 4; i += 256) {
            int r  = i >> 4;
            int d4 = (i & 15) << 2;
            const float* rp = base + (size_t)(k0 + r) * QKV_N + d4;
            float4 kv = *(const float4*)(rp + D_MODEL);
            float4 vv = *(const float4*)(rp + 2 * D_MODEL);
            Ks[r * KS_STRIDE + d4 + 0] = kv.x; Ks[r * KS_STRIDE + d4 + 1] = kv.y;
            Ks[r * KS_STRIDE + d4 + 2] = kv.z; Ks[r * KS_STRIDE + d4 + 3] = kv.w;
            Vs[r * DK + d4 + 0] = vv.x; Vs[r * DK + d4 + 1] = vv.y;
            Vs[r * DK + d4 + 2] = vv.z; Vs[r * DK + d4 + 3] = vv.w;
        }
        __syncthreads();   // also guards Qs on first iteration

        // S = Q @ K^T : 4x4 per thread
        float s[4][4];
#pragma unroll
        for (int i = 0; i < 4; i++)
#pragma unroll
            for (int j = 0; j < 4; j++) s[i][j] = 0.f;

#pragma unroll 8
        for (int d = 0; d < DK; d++) {
            float a[4], kk[4];
#pragma unroll
            for (int i = 0; i < 4; i++) a[i] = Qs[(r0 + i) * DK + d];
#pragma unroll
            for (int j = 0; j < 4; j++) kk[j] = Ks[(c0 + j) * KS_STRIDE + d];
#pragma unroll
            for (int i = 0; i < 4; i++)
#pragma unroll
                for (int j = 0; j < 4; j++)
                    s[i][j] += a[i] * kk[j];
        }

        const bool diag = (kt == qt);
#pragma unroll
        for (int i = 0; i < 4; i++) {
            const int qg = q0 + r0 + i;
            float sv[4];
            float mloc = -1e30f;
#pragma unroll
            for (int j = 0; j < 4; j++) {
                float v = s[i][j] * 0.125f;          // 1/sqrt(64)
                if (diag && (k0 + c0 + j > qg)) v = -1e30f;
                sv[j] = v;
                mloc = fmaxf(mloc, v);
            }
#pragma unroll
            for (int off = 1; off < 16; off <<= 1)
                mloc = fmaxf(mloc, __shfl_xor_sync(0xffffffffu, mloc, off));
            float mnew = fmaxf(m_i[i], mloc);
            float corr = __expf(m_i[i] - mnew);
            float lloc = 0.f;
#pragma unroll
            for (int j = 0; j < 4; j++) {
                sv[j] = __expf(sv[j] - mnew);
                lloc += sv[j];
            }
#pragma unroll
            for (int off = 1; off < 16; off <<= 1)
                lloc += __shfl_xor_sync(0xffffffffu, lloc, off);
            l_i[i] = l_i[i] * corr + lloc;
            m_i[i] = mnew;
#pragma unroll
            for (int j = 0; j < 4; j++) o[i][j] *= corr;
            s[i][0] = sv[0]; s[i][1] = sv[1]; s[i][2] = sv[2]; s[i][3] = sv[3];
        }

        // O += P @ V  (P broadcast from register via shfl, width-16 segments)
#pragma unroll 1
        for (int cb = 0; cb < 16; cb++) {
#pragma unroll
            for (int jj = 0; jj < 4; jj++) {
                const int c = cb * 4 + jj;
                float p0 = __shfl_sync(0xffffffffu, s[0][jj], cb, 16);
                float p1 = __shfl_sync(0xffffffffu, s[1][jj], cb, 16);
                float p2 = __shfl_sync(0xffffffffu, s[2][jj], cb, 16);
                float p3 = __shfl_sync(0xffffffffu, s[3][jj], cb, 16);
                float v0 = Vs[c * DK + c0 + 0];
                float v1 = Vs[c * DK + c0 + 1];
                float v2 = Vs[c * DK + c0 + 2];
                float v3 = Vs[c * DK + c0 + 3];
                o[0][0] += p0 * v0; o[0][1] += p0 * v1; o[0][2] += p0 * v2; o[0][3] += p0 * v3;
                o[1][0] += p1 * v0; o[1][1] += p1 * v1; o[1][2] += p1 * v2; o[1][3] += p1 * v3;
                o[2][0] += p2 * v0; o[2][1] += p2 * v1; o[2][2] += p2 * v2; o[2][3] += p2 * v3;
                o[3][0] += p3 * v0; o[3][1] += p3 * v1; o[3][2] += p3 * v2; o[3][3] += p3 * v3;
            }
        }
        __syncthreads();   // before next tile overwrites Ks/Vs
    }

    // Finalize: divide by l, write [b, s, h*64 + d] layout (row-major [4096,1024])
#pragma unroll
    for (int i = 0; i < 4; i++) {
        float inv = 1.f / l_i[i];
        size_t row = (size_t)(b * SEQ + q0 + r0 + i) * D_MODEL + h * DK + c0;
        att[row + 0] = o[i][0] * inv;
        att[row + 1] = o[i][1] * inv;
        att[row + 2] = o[i][2] * inv;
        att[row + 3] = o[i][3] * inv;
    }
}

// ---------------------------------------------------------------------------
extern "C" void kernel_launch(void* const* d_in, const int* in_sizes, int n_in,
                              void* d_out, int out_size)
{
    const float* x       = (const float*)d_in[0];
    // d_in[1] = causal mask (int32) — structure is known causal; unused
    const float* w_qkv_w = (const float*)d_in[2];
    const float* w_qkv_b = (const float*)d_in[3];
    const float* w_o_w   = (const float*)d_in[4];
    const float* w_o_b   = (const float*)d_in[5];
    float* out = (float*)d_out;

    float *qkv, *att;
    cudaGetSymbolAddress((void**)&qkv, g_qkv);
    cudaGetSymbolAddress((void**)&att, g_att);

    cudaFuncSetAttribute(flash_attn, cudaFuncAttributeMaxDynamicSharedMemorySize, ATT_SMEM);

    // 1) QKV projection: [4096,1024] @ [3072,1024]^T -> [4096,3072]
    dim3 g1(QKV_N / GTN, MTOK / GTM);
    sgemm_nt_bias<<<g1, 256>>>(x, w_qkv_w, w_qkv_b, qkv, MTOK, QKV_N, D_MODEL);

    // 2) Causal flash attention -> [4096,1024]
    dim3 g2(SEQ / BQ, NH, BATCH);
    flash_attn<<<g2, 256, ATT_SMEM>>>(qkv, att);

    // 3) Output projection: [4096,1024] @ [1024,1024]^T -> [4096,1024]
    dim3 g3(D_MODEL / GTN, MTOK / GTM);
    sgemm_nt_bias<<<g3, 256>>>(att, w_o_w, w_o_b, out, MTOK, D_MODEL, D_MODEL);
}

// round 5
// speedup vs baseline: 1.8036x; 1.8036x over previous
#include <cuda_runtime.h>
#include <cstdint>

#define D_MODEL 1024
#define NH      16
#define DK      64
#define BATCH   2
#define SEQ     2048
#define MTOK    (BATCH*SEQ)     // 4096
#define QKV_N   (3*D_MODEL)     // 3072

// Scratch (alloc-free rule: __device__ globals)
__device__ float g_qkv[(size_t)MTOK * QKV_N];   // [4096, 3072]
__device__ float g_att[(size_t)MTOK * D_MODEL]; // [4096, 1024]

// ---------------------------------------------------------------------------
// tf32 helpers (legacy mma.sync path — works on base sm_103 target)
// ---------------------------------------------------------------------------
__device__ __forceinline__ uint32_t f2tf32(float x) {
    uint32_t u;
    asm("cvt.rna.tf32.f32 %0, %1;" : "=r"(u) : "f"(x));
    return u;
}

__device__ __forceinline__ void mma_tf32_16x8x8(
    float* c, const uint32_t* a, const uint32_t* b)
{
    asm volatile(
        "mma.sync.aligned.m16n8k8.row.col.f32.tf32.tf32.f32 "
        "{%0,%1,%2,%3}, {%4,%5,%6,%7}, {%8,%9}, {%0,%1,%2,%3};"
        : "+f"(c[0]), "+f"(c[1]), "+f"(c[2]), "+f"(c[3])
        : "r"(a[0]), "r"(a[1]), "r"(a[2]), "r"(a[3]),
          "r"(b[0]), "r"(b[1]));
}

// ---------------------------------------------------------------------------
// tf32 mma.sync GEMM: C[M,N] = A[M,K] @ B[N,K]^T + bias[N]
// CTA 128x128, K-chunk 32, 128 threads = 4 warps, warp tile 64x64.
// Smem stride 36 floats -> conflict-free fragment LDS.
// ---------------------------------------------------------------------------
#define GKT 32
#define SSTR 36

__global__ __launch_bounds__(128) void gemm_mma_tf32(
    const float* __restrict__ A, const float* __restrict__ Bm,
    const float* __restrict__ bias, float* __restrict__ C,
    int M, int N, int K)
{
    __shared__ float As[128 * SSTR];   // A tile [m][k], tf32-rounded
    __shared__ float Bs[128 * SSTR];   // B tile [n][k]

    const int tid = threadIdx.x;
    const int w   = tid >> 5;
    const int l   = tid & 31;
    const int gid = l >> 2;            // 0..7
    const int t4  = l & 3;             // 0..3
    const int wm  = (w & 1) * 64;
    const int wn  = (w >> 1) * 64;
    const int row0 = blockIdx.y * 128;
    const int col0 = blockIdx.x * 128;

    float acc[4][8][4];
#pragma unroll
    for (int mi = 0; mi < 4; mi++)
#pragma unroll
        for (int ni = 0; ni < 8; ni++)
#pragma unroll
            for (int q = 0; q < 4; q++) acc[mi][ni][q] = 0.f;

    for (int k0 = 0; k0 < K; k0 += GKT) {
        // Stage A and B tiles (128 rows x 32 k), tf32 RNA-rounded
#pragma unroll
        for (int j = 0; j < 8; j++) {
            int i  = tid + 128 * j;
            int r  = i >> 3;
            int c4 = (i & 7) * 4;
            float4 a = *(const float4*)(A  + (size_t)(row0 + r) * K + k0 + c4);
            float4 b = *(const float4*)(Bm + (size_t)(col0 + r) * K + k0 + c4);
            uint4 au = make_uint4(f2tf32(a.x), f2tf32(a.y), f2tf32(a.z), f2tf32(a.w));
            uint4 bu = make_uint4(f2tf32(b.x), f2tf32(b.y), f2tf32(b.z), f2tf32(b.w));
            *(uint4*)&As[r * SSTR + c4] = au;
            *(uint4*)&Bs[r * SSTR + c4] = bu;
        }
        __syncthreads();

#pragma unroll
        for (int ks = 0; ks < 4; ks++) {
            const int k8 = ks * 8;
            uint32_t af[4][4];
#pragma unroll
            for (int mi = 0; mi < 4; mi++) {
                int m = wm + mi * 16 + gid;
                af[mi][0] = __float_as_uint(As[m * SSTR + k8 + t4]);
                af[mi][1] = __float_as_uint(As[(m + 8) * SSTR + k8 + t4]);
                af[mi][2] = __float_as_uint(As[m * SSTR + k8 + t4 + 4]);
                af[mi][3] = __float_as_uint(As[(m + 8) * SSTR + k8 + t4 + 4]);
            }
            uint32_t bf[8][2];
#pragma unroll
            for (int ni = 0; ni < 8; ni++) {
                int n = wn + ni * 8 + gid;
                bf[ni][0] = __float_as_uint(Bs[n * SSTR + k8 + t4]);
                bf[ni][1] = __float_as_uint(Bs[n * SSTR + k8 + t4 + 4]);
            }
#pragma unroll
            for (int mi = 0; mi < 4; mi++)
#pragma unroll
                for (int ni = 0; ni < 8; ni++)
                    mma_tf32_16x8x8(acc[mi][ni], af[mi], bf[ni]);
        }
        __syncthreads();
    }

    // Epilogue: c0,c1 -> (row gid, cols 2*t4, 2*t4+1); c2,c3 -> row gid+8
#pragma unroll
    for (int mi = 0; mi < 4; mi++) {
        int m = row0 + wm + mi * 16 + gid;
#pragma unroll
        for (int ni = 0; ni < 8; ni++) {
            int n = col0 + wn + ni * 8 + 2 * t4;
            float b0 = bias[n], b1 = bias[n + 1];
            float2 v0 = make_float2(acc[mi][ni][0] + b0, acc[mi][ni][1] + b1);
            float2 v1 = make_float2(acc[mi][ni][2] + b0, acc[mi][ni][3] + b1);
            *(float2*)&C[(size_t)m * N + n] = v0;
            *(float2*)&C[(size_t)(m + 8) * N + n] = v1;
        }
    }
}

// ---------------------------------------------------------------------------
// Flash attention (causal), fp32. One block = 64 queries of one (b, h).
// 256 threads = 16x16; thread owns 4x4 of S-tile and 4x4 of O (over dk).
// ---------------------------------------------------------------------------
#define BQ  64
#define BKT 64
#define KS_STRIDE (DK + 1)
#define ATT_SMEM ((BQ*DK + BKT*KS_STRIDE + BKT*DK) * (int)sizeof(float))  // 49408

__global__ __launch_bounds__(256) void flash_attn(
    const float* __restrict__ qkv, float* __restrict__ att)
{
    extern __shared__ float sm[];
    float* Qs = sm;                       // [64][64]
    float* Ks = Qs + BQ * DK;             // [64][65] padded
    float* Vs = Ks + BKT * KS_STRIDE;     // [64][64]

    const int qt  = blockIdx.x;
    const int h   = blockIdx.y;
    const int b   = blockIdx.z;
    const int tid = threadIdx.x;
    const int tx  = tid & 15;
    const int ty  = tid >> 4;
    const int r0  = ty * 4;
    const int c0  = tx * 4;
    const int q0  = qt * BQ;

    const float* base = qkv + (size_t)b * SEQ * QKV_N + h * DK;

    for (int i = tid; i < BQ * DK / 4; i += 256) {
        int r  = i >> 4;
        int d4 = (i & 15) << 2;
        float4 v = *(const float4*)(base + (size_t)(q0 + r) * QKV_N + d4);
        Qs[r * DK + d4 + 0] = v.x; Qs[r * DK + d4 + 1] = v.y;
        Qs[r * DK + d4 + 2] = v.z; Qs[r * DK + d4 + 3] = v.w;
    }

    float m_i[4], l_i[4], o[4][4];
#pragma unroll
    for (int i = 0; i < 4; i++) {
        m_i[i] = -1e30f; l_i[i] = 0.f;
#pragma unroll
        for (int j = 0; j < 4; j++) o[i][j] = 0.f;
    }

    for (int kt = 0; kt <= qt; kt++) {
        const int k0 = kt * BKT;
        for (int i = tid; i < BKT * DK / 4; i += 256) {
            int r  = i >> 4;
            int d4 = (i & 15) << 2;
            const float* rp = base + (size_t)(k0 + r) * QKV_N + d4;
            float4 kv = *(const float4*)(rp + D_MODEL);
            float4 vv = *(const float4*)(rp + 2 * D_MODEL);
            Ks[r * KS_STRIDE + d4 + 0] = kv.x; Ks[r * KS_STRIDE + d4 + 1] = kv.y;
            Ks[r * KS_STRIDE + d4 + 2] = kv.z; Ks[r * KS_STRIDE + d4 + 3] = kv.w;
            Vs[r * DK + d4 + 0] = vv.x; Vs[r * DK + d4 + 1] = vv.y;
            Vs[r * DK + d4 + 2] = vv.z; Vs[r * DK + d4 + 3] = vv.w;
        }
        __syncthreads();

        float s[4][4];
#pragma unroll
        for (int i = 0; i < 4; i++)
#pragma unroll
            for (int j = 0; j < 4; j++) s[i][j] = 0.f;

#pragma unroll 8
        for (int d = 0; d < DK; d++) {
            float a[4], kk[4];
#pragma unroll
            for (int i = 0; i < 4; i++) a[i] = Qs[(r0 + i) * DK + d];
#pragma unroll
            for (int j = 0; j < 4; j++) kk[j] = Ks[(c0 + j) * KS_STRIDE + d];
#pragma unroll
            for (int i = 0; i < 4; i++)
#pragma unroll
                for (int j = 0; j < 4; j++)
                    s[i][j] += a[i] * kk[j];
        }

        const bool diag = (kt == qt);
#pragma unroll
        for (int i = 0; i < 4; i++) {
            const int qg = q0 + r0 + i;
            float sv[4];
            float mloc = -1e30f;
#pragma unroll
            for (int j = 0; j < 4; j++) {
                float v = s[i][j] * 0.125f;
                if (diag && (k0 + c0 + j > qg)) v = -1e30f;
                sv[j] = v;
                mloc = fmaxf(mloc, v);
            }
#pragma unroll
            for (int off = 1; off < 16; off <<= 1)
                mloc = fmaxf(mloc, __shfl_xor_sync(0xffffffffu, mloc, off));
            float mnew = fmaxf(m_i[i], mloc);
            float corr = __expf(m_i[i] - mnew);
            float lloc = 0.f;
#pragma unroll
            for (int j = 0; j < 4; j++) {
                sv[j] = __expf(sv[j] - mnew);
                lloc += sv[j];
            }
#pragma unroll
            for (int off = 1; off < 16; off <<= 1)
                lloc += __shfl_xor_sync(0xffffffffu, lloc, off);
            l_i[i] = l_i[i] * corr + lloc;
            m_i[i] = mnew;
#pragma unroll
            for (int j = 0; j < 4; j++) o[i][j] *= corr;
            s[i][0] = sv[0]; s[i][1] = sv[1]; s[i][2] = sv[2]; s[i][3] = sv[3];
        }

#pragma unroll 1
        for (int cb = 0; cb < 16; cb++) {
#pragma unroll
            for (int jj = 0; jj < 4; jj++) {
                const int c = cb * 4 + jj;
                float p0 = __shfl_sync(0xffffffffu, s[0][jj], cb, 16);
                float p1 = __shfl_sync(0xffffffffu, s[1][jj], cb, 16);
                float p2 = __shfl_sync(0xffffffffu, s[2][jj], cb, 16);
                float p3 = __shfl_sync(0xffffffffu, s[3][jj], cb, 16);
                float v0 = Vs[c * DK + c0 + 0];
                float v1 = Vs[c * DK + c0 + 1];
                float v2 = Vs[c * DK + c0 + 2];
                float v3 = Vs[c * DK + c0 + 3];
                o[0][0] += p0 * v0; o[0][1] += p0 * v1; o[0][2] += p0 * v2; o[0][3] += p0 * v3;
                o[1][0] += p1 * v0; o[1][1] += p1 * v1; o[1][2] += p1 * v2; o[1][3] += p1 * v3;
                o[2][0] += p2 * v0; o[2][1] += p2 * v1; o[2][2] += p2 * v2; o[2][3] += p2 * v3;
                o[3][0] += p3 * v0; o[3][1] += p3 * v1; o[3][2] += p3 * v2; o[3][3] += p3 * v3;
            }
        }
        __syncthreads();
    }

#pragma unroll
    for (int i = 0; i < 4; i++) {
        float inv = 1.f / l_i[i];
        size_t row = (size_t)(b * SEQ + q0 + r0 + i) * D_MODEL + h * DK + c0;
        att[row + 0] = o[i][0] * inv;
        att[row + 1] = o[i][1] * inv;
        att[row + 2] = o[i][2] * inv;
        att[row + 3] = o[i][3] * inv;
    }
}

// ---------------------------------------------------------------------------
extern "C" void kernel_launch(void* const* d_in, const int* in_sizes, int n_in,
                              void* d_out, int out_size)
{
    const float* x       = (const float*)d_in[0];
    // d_in[1] = causal mask (int32) — structure is known causal; unused
    const float* w_qkv_w = (const float*)d_in[2];
    const float* w_qkv_b = (const float*)d_in[3];
    const float* w_o_w   = (const float*)d_in[4];
    const float* w_o_b   = (const float*)d_in[5];
    float* out = (float*)d_out;

    float *qkv, *att;
    cudaGetSymbolAddress((void**)&qkv, g_qkv);
    cudaGetSymbolAddress((void**)&att, g_att);

    cudaFuncSetAttribute(flash_attn, cudaFuncAttributeMaxDynamicSharedMemorySize, ATT_SMEM);

    // 1) QKV projection: [4096,1024] @ [3072,1024]^T -> [4096,3072]
    dim3 g1(QKV_N / 128, MTOK / 128);
    gemm_mma_tf32<<<g1, 128>>>(x, w_qkv_w, w_qkv_b, qkv, MTOK, QKV_N, D_MODEL);

    // 2) Causal flash attention -> [4096,1024]
    dim3 g2(SEQ / BQ, NH, BATCH);
    flash_attn<<<g2, 256, ATT_SMEM>>>(qkv, att);

    // 3) Output projection: [4096,1024] @ [1024,1024]^T -> [4096,1024]
    dim3 g3(D_MODEL / 128, MTOK / 128);
    gemm_mma_tf32<<<g3, 128>>>(att, w_o_w, w_o_b, out, MTOK, D_MODEL, D_MODEL);
}

// round 6
// speedup vs baseline: 2.6136x; 1.4491x over previous
#include <cuda_runtime.h>
#include <cstdint>

#define D_MODEL 1024
#define NH      16
#define DK      64
#define BATCH   2
#define SEQ     2048
#define MTOK    (BATCH*SEQ)     // 4096
#define QKV_N   (3*D_MODEL)     // 3072

// Scratch (alloc-free rule: __device__ globals)
__device__ float g_qkv[(size_t)MTOK * QKV_N];   // [4096, 3072]
__device__ float g_att[(size_t)MTOK * D_MODEL]; // [4096, 1024]

// ---------------------------------------------------------------------------
// tf32 helpers (legacy mma.sync path — works on base sm_103 target)
// ---------------------------------------------------------------------------
__device__ __forceinline__ uint32_t f2tf32(float x) {
    uint32_t u;
    asm("cvt.rna.tf32.f32 %0, %1;" : "=r"(u) : "f"(x));
    return u;
}

__device__ __forceinline__ void mma_tf32_16x8x8(
    float* c, const uint32_t* a, const uint32_t* b)
{
    asm volatile(
        "mma.sync.aligned.m16n8k8.row.col.f32.tf32.tf32.f32 "
        "{%0,%1,%2,%3}, {%4,%5,%6,%7}, {%8,%9}, {%0,%1,%2,%3};"
        : "+f"(c[0]), "+f"(c[1]), "+f"(c[2]), "+f"(c[3])
        : "r"(a[0]), "r"(a[1]), "r"(a[2]), "r"(a[3]),
          "r"(b[0]), "r"(b[1]));
}

// ---------------------------------------------------------------------------
// tf32 mma.sync GEMM: C[M,N] = A[M,K] @ B[N,K]^T + bias[N]
// CTA 128x128, K-chunk 32, 128 threads = 4 warps, warp tile 64x64.
// ---------------------------------------------------------------------------
#define GKT 32
#define SSTR 36

__global__ __launch_bounds__(128) void gemm_mma_tf32(
    const float* __restrict__ A, const float* __restrict__ Bm,
    const float* __restrict__ bias, float* __restrict__ C,
    int M, int N, int K)
{
    __shared__ float As[128 * SSTR];
    __shared__ float Bs[128 * SSTR];

    const int tid = threadIdx.x;
    const int w   = tid >> 5;
    const int l   = tid & 31;
    const int gid = l >> 2;
    const int t4  = l & 3;
    const int wm  = (w & 1) * 64;
    const int wn  = (w >> 1) * 64;
    const int row0 = blockIdx.y * 128;
    const int col0 = blockIdx.x * 128;

    float acc[4][8][4];
#pragma unroll
    for (int mi = 0; mi < 4; mi++)
#pragma unroll
        for (int ni = 0; ni < 8; ni++)
#pragma unroll
            for (int q = 0; q < 4; q++) acc[mi][ni][q] = 0.f;

    for (int k0 = 0; k0 < K; k0 += GKT) {
#pragma unroll
        for (int j = 0; j < 8; j++) {
            int i  = tid + 128 * j;
            int r  = i >> 3;
            int c4 = (i & 7) * 4;
            float4 a = *(const float4*)(A  + (size_t)(row0 + r) * K + k0 + c4);
            float4 b = *(const float4*)(Bm + (size_t)(col0 + r) * K + k0 + c4);
            uint4 au = make_uint4(f2tf32(a.x), f2tf32(a.y), f2tf32(a.z), f2tf32(a.w));
            uint4 bu = make_uint4(f2tf32(b.x), f2tf32(b.y), f2tf32(b.z), f2tf32(b.w));
            *(uint4*)&As[r * SSTR + c4] = au;
            *(uint4*)&Bs[r * SSTR + c4] = bu;
        }
        __syncthreads();

#pragma unroll
        for (int ks = 0; ks < 4; ks++) {
            const int k8 = ks * 8;
            uint32_t af[4][4];
#pragma unroll
            for (int mi = 0; mi < 4; mi++) {
                int m = wm + mi * 16 + gid;
                af[mi][0] = __float_as_uint(As[m * SSTR + k8 + t4]);
                af[mi][1] = __float_as_uint(As[(m + 8) * SSTR + k8 + t4]);
                af[mi][2] = __float_as_uint(As[m * SSTR + k8 + t4 + 4]);
                af[mi][3] = __float_as_uint(As[(m + 8) * SSTR + k8 + t4 + 4]);
            }
            uint32_t bf[8][2];
#pragma unroll
            for (int ni = 0; ni < 8; ni++) {
                int n = wn + ni * 8 + gid;
                bf[ni][0] = __float_as_uint(Bs[n * SSTR + k8 + t4]);
                bf[ni][1] = __float_as_uint(Bs[n * SSTR + k8 + t4 + 4]);
            }
#pragma unroll
            for (int mi = 0; mi < 4; mi++)
#pragma unroll
                for (int ni = 0; ni < 8; ni++)
                    mma_tf32_16x8x8(acc[mi][ni], af[mi], bf[ni]);
        }
        __syncthreads();
    }

#pragma unroll
    for (int mi = 0; mi < 4; mi++) {
        int m = row0 + wm + mi * 16 + gid;
#pragma unroll
        for (int ni = 0; ni < 8; ni++) {
            int n = col0 + wn + ni * 8 + 2 * t4;
            float b0 = bias[n], b1 = bias[n + 1];
            float2 v0 = make_float2(acc[mi][ni][0] + b0, acc[mi][ni][1] + b1);
            float2 v1 = make_float2(acc[mi][ni][2] + b0, acc[mi][ni][3] + b1);
            *(float2*)&C[(size_t)m * N + n] = v0;
            *(float2*)&C[(size_t)(m + 8) * N + n] = v1;
        }
    }
}

// ---------------------------------------------------------------------------
// Flash attention (causal) on tf32 mma.sync.
// CTA: 128 queries of one (b,h), 4 warps x 32-query warp tile; key tile 64.
// ---------------------------------------------------------------------------
#define QSTR 68   // == 4 (mod 32): conflict-free A/B fragment LDS
#define KSTR 68
#define VSTR 72   // == 8 (mod 32): conflict-free V B-fragment LDS
#define FA_SMEM ((128*QSTR + 64*KSTR + 64*VSTR) * (int)sizeof(float))  // 70656

__global__ __launch_bounds__(128) void flash_attn_mma(
    const float* __restrict__ qkv, float* __restrict__ att)
{
    extern __shared__ float sm[];
    float* Qs = sm;                  // [128][QSTR]
    float* Ks = Qs + 128 * QSTR;     // [64][KSTR]
    float* Vs = Ks + 64 * KSTR;      // [64][VSTR]

    const int qt  = blockIdx.x;      // 0..15
    const int h   = blockIdx.y;
    const int b   = blockIdx.z;
    const int tid = threadIdx.x;
    const int w   = tid >> 5;
    const int l   = tid & 31;
    const int gid = l >> 2;
    const int t4  = l & 3;
    const int q0  = qt * 128;
    const int wq  = w * 32;
    const int q0w = q0 + wq;

    const float* base = qkv + (size_t)b * SEQ * QKV_N + h * DK;

    // Stage Q tile 128x64 (tf32-rounded)
#pragma unroll
    for (int j = 0; j < 16; j++) {
        int i  = tid + 128 * j;
        int r  = i >> 4;
        int c4 = (i & 15) * 4;
        float4 v = *(const float4*)(base + (size_t)(q0 + r) * QKV_N + c4);
        uint4 u = make_uint4(f2tf32(v.x), f2tf32(v.y), f2tf32(v.z), f2tf32(v.w));
        *(uint4*)&Qs[r * QSTR + c4] = u;
    }

    float oacc[2][8][4];
    float m_i[2][2], l_i[2][2];
#pragma unroll
    for (int mi = 0; mi < 2; mi++) {
#pragma unroll
        for (int hf = 0; hf < 2; hf++) { m_i[mi][hf] = -1e30f; l_i[mi][hf] = 0.f; }
#pragma unroll
        for (int dj = 0; dj < 8; dj++)
#pragma unroll
            for (int q = 0; q < 4; q++) oacc[mi][dj][q] = 0.f;
    }

    const int src1 = (l & ~3) | (t4 >> 1);
    const int src2 = src1 + 2;
    const bool odd = (t4 & 1);

    const int ntiles = 2 * qt + 2;
    for (int kt = 0; kt < ntiles; kt++) {
        const int k0 = kt * 64;

        // Stage K, V tiles (tf32-rounded)
#pragma unroll
        for (int j = 0; j < 8; j++) {
            int i  = tid + 128 * j;
            int r  = i >> 4;
            int c4 = (i & 15) * 4;
            const float* rp = base + (size_t)(k0 + r) * QKV_N + c4;
            float4 kv = *(const float4*)(rp + D_MODEL);
            float4 vv = *(const float4*)(rp + 2 * D_MODEL);
            *(uint4*)&Ks[r * KSTR + c4] =
                make_uint4(f2tf32(kv.x), f2tf32(kv.y), f2tf32(kv.z), f2tf32(kv.w));
            *(uint4*)&Vs[r * VSTR + c4] =
                make_uint4(f2tf32(vv.x), f2tf32(vv.y), f2tf32(vv.z), f2tf32(vv.w));
        }
        __syncthreads();

        if (k0 <= q0w + 31) {   // warp-uniform: this warp has unmasked keys here
            // ---- S = Q @ K^T (warp tile 32x64) ----
            float sacc[2][8][4];
#pragma unroll
            for (int mi = 0; mi < 2; mi++)
#pragma unroll
                for (int nj = 0; nj < 8; nj++)
#pragma unroll
                    for (int q = 0; q < 4; q++) sacc[mi][nj][q] = 0.f;

#pragma unroll
            for (int kc = 0; kc < 8; kc++) {
                const int k8 = kc * 8;
                uint32_t af[2][4];
#pragma unroll
                for (int mi = 0; mi < 2; mi++) {
                    int m = wq + mi * 16 + gid;
                    af[mi][0] = __float_as_uint(Qs[m * QSTR + k8 + t4]);
                    af[mi][1] = __float_as_uint(Qs[(m + 8) * QSTR + k8 + t4]);
                    af[mi][2] = __float_as_uint(Qs[m * QSTR + k8 + t4 + 4]);
                    af[mi][3] = __float_as_uint(Qs[(m + 8) * QSTR + k8 + t4 + 4]);
                }
#pragma unroll
                for (int nj = 0; nj < 8; nj++) {
                    uint32_t bf[2];
                    bf[0] = __float_as_uint(Ks[(nj * 8 + gid) * KSTR + k8 + t4]);
                    bf[1] = __float_as_uint(Ks[(nj * 8 + gid) * KSTR + k8 + t4 + 4]);
                    mma_tf32_16x8x8(sacc[0][nj], af[0], bf);
                    mma_tf32_16x8x8(sacc[1][nj], af[1], bf);
                }
            }

            // ---- online softmax ----
            const bool domask = (k0 + 63 > q0w);
#pragma unroll
            for (int mi = 0; mi < 2; mi++) {
#pragma unroll
                for (int hf = 0; hf < 2; hf++) {
                    const int qrow = q0w + mi * 16 + hf * 8 + gid;
                    float mloc = -1e30f;
#pragma unroll
                    for (int nj = 0; nj < 8; nj++) {
#pragma unroll
                        for (int c = 0; c < 2; c++) {
                            float v = sacc[mi][nj][2 * hf + c] * 0.125f;
                            if (domask && (k0 + nj * 8 + 2 * t4 + c > qrow)) v = -1e30f;
                            sacc[mi][nj][2 * hf + c] = v;
                            mloc = fmaxf(mloc, v);
                        }
                    }
                    mloc = fmaxf(mloc, __shfl_xor_sync(0xffffffffu, mloc, 1));
                    mloc = fmaxf(mloc, __shfl_xor_sync(0xffffffffu, mloc, 2));
                    float mnew = fmaxf(m_i[mi][hf], mloc);
                    float corr = __expf(m_i[mi][hf] - mnew);
                    float ls = 0.f;
#pragma unroll
                    for (int nj = 0; nj < 8; nj++) {
#pragma unroll
                        for (int c = 0; c < 2; c++) {
                            float p = __expf(sacc[mi][nj][2 * hf + c] - mnew);
                            sacc[mi][nj][2 * hf + c] = p;
                            ls += p;
                        }
                    }
                    ls += __shfl_xor_sync(0xffffffffu, ls, 1);
                    ls += __shfl_xor_sync(0xffffffffu, ls, 2);
                    l_i[mi][hf] = l_i[mi][hf] * corr + ls;
                    m_i[mi][hf] = mnew;
#pragma unroll
                    for (int dj = 0; dj < 8; dj++) {
                        oacc[mi][dj][2 * hf + 0] *= corr;
                        oacc[mi][dj][2 * hf + 1] *= corr;
                    }
                }
            }

            // ---- O += P @ V  (P: C-frag -> A-frag via quad shuffles) ----
#pragma unroll
            for (int kc = 0; kc < 8; kc++) {
                uint32_t pa[2][4];
#pragma unroll
                for (int mi = 0; mi < 2; mi++) {
                    float e0 = __shfl_sync(0xffffffffu, sacc[mi][kc][0], src1);
                    float e1 = __shfl_sync(0xffffffffu, sacc[mi][kc][1], src1);
                    float e2 = __shfl_sync(0xffffffffu, sacc[mi][kc][2], src1);
                    float e3 = __shfl_sync(0xffffffffu, sacc[mi][kc][3], src1);
                    float f0 = __shfl_sync(0xffffffffu, sacc[mi][kc][0], src2);
                    float f1 = __shfl_sync(0xffffffffu, sacc[mi][kc][1], src2);
                    float f2 = __shfl_sync(0xffffffffu, sacc[mi][kc][2], src2);
                    float f3 = __shfl_sync(0xffffffffu, sacc[mi][kc][3], src2);
                    pa[mi][0] = f2tf32(odd ? e1 : e0);
                    pa[mi][1] = f2tf32(odd ? e3 : e2);
                    pa[mi][2] = f2tf32(odd ? f1 : f0);
                    pa[mi][3] = f2tf32(odd ? f3 : f2);
                }
#pragma unroll
                for (int dj = 0; dj < 8; dj++) {
                    uint32_t vb[2];
                    vb[0] = __float_as_uint(Vs[(kc * 8 + t4) * VSTR + dj * 8 + gid]);
                    vb[1] = __float_as_uint(Vs[(kc * 8 + t4 + 4) * VSTR + dj * 8 + gid]);
                    mma_tf32_16x8x8(oacc[0][dj], pa[0], vb);
                    mma_tf32_16x8x8(oacc[1][dj], pa[1], vb);
                }
            }
        }
        __syncthreads();
    }

    // Finalize: divide by l and write [b*S+q][h*64+d]
#pragma unroll
    for (int mi = 0; mi < 2; mi++) {
#pragma unroll
        for (int hf = 0; hf < 2; hf++) {
            float inv = 1.f / l_i[mi][hf];
            size_t row = (size_t)(b * SEQ + q0w + mi * 16 + hf * 8 + gid) * D_MODEL
                       + h * DK;
#pragma unroll
            for (int dj = 0; dj < 8; dj++) {
                float2 v = make_float2(oacc[mi][dj][2 * hf + 0] * inv,
                                       oacc[mi][dj][2 * hf + 1] * inv);
                *(float2*)&att[row + dj * 8 + 2 * t4] = v;
            }
        }
    }
}

// ---------------------------------------------------------------------------
extern "C" void kernel_launch(void* const* d_in, const int* in_sizes, int n_in,
                              void* d_out, int out_size)
{
    const float* x       = (const float*)d_in[0];
    // d_in[1] = causal mask (int32) — structure is known causal; unused
    const float* w_qkv_w = (const float*)d_in[2];
    const float* w_qkv_b = (const float*)d_in[3];
    const float* w_o_w   = (const float*)d_in[4];
    const float* w_o_b   = (const float*)d_in[5];
    float* out = (float*)d_out;

    float *qkv, *att;
    cudaGetSymbolAddress((void**)&qkv, g_qkv);
    cudaGetSymbolAddress((void**)&att, g_att);

    cudaFuncSetAttribute(flash_attn_mma,
                         cudaFuncAttributeMaxDynamicSharedMemorySize, FA_SMEM);

    // 1) QKV projection: [4096,1024] @ [3072,1024]^T -> [4096,3072]
    dim3 g1(QKV_N / 128, MTOK / 128);
    gemm_mma_tf32<<<g1, 128>>>(x, w_qkv_w, w_qkv_b, qkv, MTOK, QKV_N, D_MODEL);

    // 2) Causal flash attention (tensor cores) -> [4096,1024]
    dim3 g2(SEQ / 128, NH, BATCH);
    flash_attn_mma<<<g2, 128, FA_SMEM>>>(qkv, att);

    // 3) Output projection: [4096,1024] @ [1024,1024]^T -> [4096,1024]
    dim3 g3(D_MODEL / 128, MTOK / 128);
    gemm_mma_tf32<<<g3, 128>>>(att, w_o_w, w_o_b, out, MTOK, D_MODEL, D_MODEL);
}

// round 7
// speedup vs baseline: 3.1960x; 1.2229x over previous
#include <cuda_runtime.h>
#include <cstdint>

#define D_MODEL 1024
#define NH      16
#define DK      64
#define BATCH   2
#define SEQ     2048
#define MTOK    (BATCH*SEQ)     // 4096
#define QKV_N   (3*D_MODEL)     // 3072

// Scratch (alloc-free rule: __device__ globals)
__device__ float g_qkv[(size_t)MTOK * QKV_N];   // [4096, 3072]
__device__ float g_att[(size_t)MTOK * D_MODEL]; // [4096, 1024]

// ---------------------------------------------------------------------------
// tf32 helpers (legacy mma.sync path — works on base sm_103 target)
// ---------------------------------------------------------------------------
__device__ __forceinline__ uint32_t f2tf32(float x) {
    uint32_t u;
    asm("cvt.rna.tf32.f32 %0, %1;" : "=r"(u) : "f"(x));
    return u;
}

__device__ __forceinline__ void mma_tf32_16x8x8(
    float* c, const uint32_t* a, const uint32_t* b)
{
    asm volatile(
        "mma.sync.aligned.m16n8k8.row.col.f32.tf32.tf32.f32 "
        "{%0,%1,%2,%3}, {%4,%5,%6,%7}, {%8,%9}, {%0,%1,%2,%3};"
        : "+f"(c[0]), "+f"(c[1]), "+f"(c[2]), "+f"(c[3])
        : "r"(a[0]), "r"(a[1]), "r"(a[2]), "r"(a[3]),
          "r"(b[0]), "r"(b[1]));
}

// ---------------------------------------------------------------------------
// tf32 mma.sync GEMM: C[M,N] = A[M,K] @ B[N,K]^T + bias[N]
// CTA 128x128, 256 threads = 8 warps, warp tile 64x32, K-chunk 32.
// Software-pipelined: double smem buffer + register-staged prefetch.
// ---------------------------------------------------------------------------
#define GKT 32
#define SSTR 36
#define G_STAGE (2 * 128 * SSTR)                 // floats per stage (As+Bs)
#define GEMM_SMEM (2 * G_STAGE * (int)sizeof(float))  // 73728 B

__global__ __launch_bounds__(256) void gemm_mma_tf32(
    const float* __restrict__ A, const float* __restrict__ Bm,
    const float* __restrict__ bias, float* __restrict__ C,
    int M, int N, int K)
{
    extern __shared__ float smem[];

    const int tid = threadIdx.x;
    const int w   = tid >> 5;
    const int l   = tid & 31;
    const int gid = l >> 2;
    const int t4  = l & 3;
    const int wm  = (w & 1) * 64;
    const int wn  = (w >> 1) * 32;
    const int row0 = blockIdx.y * 128;
    const int col0 = blockIdx.x * 128;

    float acc[4][4][4];
#pragma unroll
    for (int mi = 0; mi < 4; mi++)
#pragma unroll
        for (int ni = 0; ni < 4; ni++)
#pragma unroll
            for (int q = 0; q < 4; q++) acc[mi][ni][q] = 0.f;

    // Per-thread staging coords: 4 float4 of A + 4 of B per K-chunk
    int s_r[4], s_c[4];
#pragma unroll
    for (int j = 0; j < 4; j++) {
        int idx = tid + 256 * j;
        s_r[j] = idx >> 3;
        s_c[j] = (idx & 7) * 4;
    }

    float4 pa[4], pb[4];
    // Prologue: load + store chunk 0
#pragma unroll
    for (int j = 0; j < 4; j++) {
        pa[j] = *(const float4*)(A  + (size_t)(row0 + s_r[j]) * K + s_c[j]);
        pb[j] = *(const float4*)(Bm + (size_t)(col0 + s_r[j]) * K + s_c[j]);
    }
#pragma unroll
    for (int j = 0; j < 4; j++) {
        *(uint4*)&smem[s_r[j] * SSTR + s_c[j]] =
            make_uint4(f2tf32(pa[j].x), f2tf32(pa[j].y), f2tf32(pa[j].z), f2tf32(pa[j].w));
        *(uint4*)&smem[128 * SSTR + s_r[j] * SSTR + s_c[j]] =
            make_uint4(f2tf32(pb[j].x), f2tf32(pb[j].y), f2tf32(pb[j].z), f2tf32(pb[j].w));
    }
    __syncthreads();

    const int nK = K / GKT;
    for (int it = 0; it < nK; it++) {
        // Prefetch next chunk (LDGs issue before MMA block, consumed after)
        if (it + 1 < nK) {
            const int k0 = (it + 1) * GKT;
#pragma unroll
            for (int j = 0; j < 4; j++) {
                pa[j] = *(const float4*)(A  + (size_t)(row0 + s_r[j]) * K + k0 + s_c[j]);
                pb[j] = *(const float4*)(Bm + (size_t)(col0 + s_r[j]) * K + k0 + s_c[j]);
            }
        }

        const float* As = smem + (it & 1) * G_STAGE;
        const float* Bs = As + 128 * SSTR;
#pragma unroll
        for (int ks = 0; ks < 4; ks++) {
            const int k8 = ks * 8;
            uint32_t af[4][4];
#pragma unroll
            for (int mi = 0; mi < 4; mi++) {
                int m = wm + mi * 16 + gid;
                af[mi][0] = __float_as_uint(As[m * SSTR + k8 + t4]);
                af[mi][1] = __float_as_uint(As[(m + 8) * SSTR + k8 + t4]);
                af[mi][2] = __float_as_uint(As[m * SSTR + k8 + t4 + 4]);
                af[mi][3] = __float_as_uint(As[(m + 8) * SSTR + k8 + t4 + 4]);
            }
            uint32_t bf[4][2];
#pragma unroll
            for (int ni = 0; ni < 4; ni++) {
                int n = wn + ni * 8 + gid;
                bf[ni][0] = __float_as_uint(Bs[n * SSTR + k8 + t4]);
                bf[ni][1] = __float_as_uint(Bs[n * SSTR + k8 + t4 + 4]);
            }
#pragma unroll
            for (int mi = 0; mi < 4; mi++)
#pragma unroll
                for (int ni = 0; ni < 4; ni++)
                    mma_tf32_16x8x8(acc[mi][ni], af[mi], bf[ni]);
        }

        if (it + 1 < nK) {
            float* Ad = smem + ((it + 1) & 1) * G_STAGE;
            float* Bd = Ad + 128 * SSTR;
#pragma unroll
            for (int j = 0; j < 4; j++) {
                *(uint4*)&Ad[s_r[j] * SSTR + s_c[j]] =
                    make_uint4(f2tf32(pa[j].x), f2tf32(pa[j].y), f2tf32(pa[j].z), f2tf32(pa[j].w));
                *(uint4*)&Bd[s_r[j] * SSTR + s_c[j]] =
                    make_uint4(f2tf32(pb[j].x), f2tf32(pb[j].y), f2tf32(pb[j].z), f2tf32(pb[j].w));
            }
        }
        __syncthreads();
    }

    // Epilogue
#pragma unroll
    for (int mi = 0; mi < 4; mi++) {
        int m = row0 + wm + mi * 16 + gid;
#pragma unroll
        for (int ni = 0; ni < 4; ni++) {
            int n = col0 + wn + ni * 8 + 2 * t4;
            float b0 = bias[n], b1 = bias[n + 1];
            float2 v0 = make_float2(acc[mi][ni][0] + b0, acc[mi][ni][1] + b1);
            float2 v1 = make_float2(acc[mi][ni][2] + b0, acc[mi][ni][3] + b1);
            *(float2*)&C[(size_t)m * N + n] = v0;
            *(float2*)&C[(size_t)(m + 8) * N + n] = v1;
        }
    }
}

// ---------------------------------------------------------------------------
// Flash attention (causal) on tf32 mma.sync, double-buffered K/V.
// CTA: 128 queries of one (b,h), 4 warps x 32-query warp tile; key tile 64.
// 1/sqrt(dk) folded into Q at stage time (exact: 0.125).
// ---------------------------------------------------------------------------
#define QSTR 68   // == 4 (mod 32): conflict-free A/B fragment LDS
#define KSTR 68
#define VSTR 72   // == 8 (mod 32): conflict-free V B-fragment LDS
#define KV_STAGE (64 * KSTR + 64 * VSTR)   // floats
#define FA_SMEM ((128 * QSTR + 2 * KV_STAGE) * (int)sizeof(float))  // 106496

__global__ __launch_bounds__(128) void flash_attn_mma(
    const float* __restrict__ qkv, float* __restrict__ att)
{
    extern __shared__ float sm[];
    float* Qs = sm;                       // [128][QSTR]

    const int qt  = blockIdx.x;           // 0..15
    const int h   = blockIdx.y;
    const int b   = blockIdx.z;
    const int tid = threadIdx.x;
    const int w   = tid >> 5;
    const int l   = tid & 31;
    const int gid = l >> 2;
    const int t4  = l & 3;
    const int q0  = qt * 128;
    const int wq  = w * 32;
    const int q0w = q0 + wq;

    const float* base = qkv + (size_t)b * SEQ * QKV_N + h * DK;

    // Stage Q tile 128x64, scaled by 0.125 (exact), tf32-rounded
#pragma unroll
    for (int j = 0; j < 16; j++) {
        int i  = tid + 128 * j;
        int r  = i >> 4;
        int c4 = (i & 15) * 4;
        float4 v = *(const float4*)(base + (size_t)(q0 + r) * QKV_N + c4);
        uint4 u = make_uint4(f2tf32(v.x * 0.125f), f2tf32(v.y * 0.125f),
                             f2tf32(v.z * 0.125f), f2tf32(v.w * 0.125f));
        *(uint4*)&Qs[r * QSTR + c4] = u;
    }

    // Prologue: stage K/V tile 0 into buffer 0
    {
        float* Ks = sm + 128 * QSTR;
        float* Vs = Ks + 64 * KSTR;
#pragma unroll
        for (int j = 0; j < 8; j++) {
            int i  = tid + 128 * j;
            int r  = i >> 4;
            int c4 = (i & 15) * 4;
            const float* rp = base + (size_t)r * QKV_N + c4;
            float4 kv = *(const float4*)(rp + D_MODEL);
            float4 vv = *(const float4*)(rp + 2 * D_MODEL);
            *(uint4*)&Ks[r * KSTR + c4] =
                make_uint4(f2tf32(kv.x), f2tf32(kv.y), f2tf32(kv.z), f2tf32(kv.w));
            *(uint4*)&Vs[r * VSTR + c4] =
                make_uint4(f2tf32(vv.x), f2tf32(vv.y), f2tf32(vv.z), f2tf32(vv.w));
        }
    }
    __syncthreads();

    float oacc[2][8][4];
    float m_i[2][2], l_i[2][2];
#pragma unroll
    for (int mi = 0; mi < 2; mi++) {
#pragma unroll
        for (int hf = 0; hf < 2; hf++) { m_i[mi][hf] = -1e30f; l_i[mi][hf] = 0.f; }
#pragma unroll
        for (int dj = 0; dj < 8; dj++)
#pragma unroll
            for (int q = 0; q < 4; q++) oacc[mi][dj][q] = 0.f;
    }

    const int src1 = (l & ~3) | (t4 >> 1);
    const int src2 = src1 + 2;
    const bool odd = (t4 & 1);

    const int ntiles = 2 * qt + 2;
    for (int kt = 0; kt < ntiles; kt++) {
        const int k0 = kt * 64;

        // Stage next K/V tile into the other buffer (readers of it synced out)
        if (kt + 1 < ntiles) {
            const int kn = (kt + 1) * 64;
            float* Ks = sm + 128 * QSTR + ((kt + 1) & 1) * KV_STAGE;
            float* Vs = Ks + 64 * KSTR;
#pragma unroll
            for (int j = 0; j < 8; j++) {
                int i  = tid + 128 * j;
                int r  = i >> 4;
                int c4 = (i & 15) * 4;
                const float* rp = base + (size_t)(kn + r) * QKV_N + c4;
                float4 kv = *(const float4*)(rp + D_MODEL);
                float4 vv = *(const float4*)(rp + 2 * D_MODEL);
                *(uint4*)&Ks[r * KSTR + c4] =
                    make_uint4(f2tf32(kv.x), f2tf32(kv.y), f2tf32(kv.z), f2tf32(kv.w));
                *(uint4*)&Vs[r * VSTR + c4] =
                    make_uint4(f2tf32(vv.x), f2tf32(vv.y), f2tf32(vv.z), f2tf32(vv.w));
            }
        }

        if (k0 <= q0w + 31) {   // warp-uniform: this warp has unmasked keys here
            const float* Ks = sm + 128 * QSTR + (kt & 1) * KV_STAGE;
            const float* Vs = Ks + 64 * KSTR;

            // ---- S = Q @ K^T (warp tile 32x64) ----
            float sacc[2][8][4];
#pragma unroll
            for (int mi = 0; mi < 2; mi++)
#pragma unroll
                for (int nj = 0; nj < 8; nj++)
#pragma unroll
                    for (int q = 0; q < 4; q++) sacc[mi][nj][q] = 0.f;

#pragma unroll
            for (int kc = 0; kc < 8; kc++) {
                const int k8 = kc * 8;
                uint32_t af[2][4];
#pragma unroll
                for (int mi = 0; mi < 2; mi++) {
                    int m = wq + mi * 16 + gid;
                    af[mi][0] = __float_as_uint(Qs[m * QSTR + k8 + t4]);
                    af[mi][1] = __float_as_uint(Qs[(m + 8) * QSTR + k8 + t4]);
                    af[mi][2] = __float_as_uint(Qs[m * QSTR + k8 + t4 + 4]);
                    af[mi][3] = __float_as_uint(Qs[(m + 8) * QSTR + k8 + t4 + 4]);
                }
#pragma unroll
                for (int nj = 0; nj < 8; nj++) {
                    uint32_t bf[2];
                    bf[0] = __float_as_uint(Ks[(nj * 8 + gid) * KSTR + k8 + t4]);
                    bf[1] = __float_as_uint(Ks[(nj * 8 + gid) * KSTR + k8 + t4 + 4]);
                    mma_tf32_16x8x8(sacc[0][nj], af[0], bf);
                    mma_tf32_16x8x8(sacc[1][nj], af[1], bf);
                }
            }

            // ---- online softmax (scale already folded into Q) ----
            const bool domask = (k0 + 63 > q0w);
#pragma unroll
            for (int mi = 0; mi < 2; mi++) {
#pragma unroll
                for (int hf = 0; hf < 2; hf++) {
                    const int qrow = q0w + mi * 16 + hf * 8 + gid;
                    float mloc = -1e30f;
#pragma unroll
                    for (int nj = 0; nj < 8; nj++) {
#pragma unroll
                        for (int c = 0; c < 2; c++) {
                            float v = sacc[mi][nj][2 * hf + c];
                            if (domask && (k0 + nj * 8 + 2 * t4 + c > qrow)) v = -1e30f;
                            sacc[mi][nj][2 * hf + c] = v;
                            mloc = fmaxf(mloc, v);
                        }
                    }
                    mloc = fmaxf(mloc, __shfl_xor_sync(0xffffffffu, mloc, 1));
                    mloc = fmaxf(mloc, __shfl_xor_sync(0xffffffffu, mloc, 2));
                    float mnew = fmaxf(m_i[mi][hf], mloc);
                    float corr = __expf(m_i[mi][hf] - mnew);
                    float ls = 0.f;
#pragma unroll
                    for (int nj = 0; nj < 8; nj++) {
#pragma unroll
                        for (int c = 0; c < 2; c++) {
                            float p = __expf(sacc[mi][nj][2 * hf + c] - mnew);
                            sacc[mi][nj][2 * hf + c] = p;
                            ls += p;
                        }
                    }
                    ls += __shfl_xor_sync(0xffffffffu, ls, 1);
                    ls += __shfl_xor_sync(0xffffffffu, ls, 2);
                    l_i[mi][hf] = l_i[mi][hf] * corr + ls;
                    m_i[mi][hf] = mnew;
#pragma unroll
                    for (int dj = 0; dj < 8; dj++) {
                        oacc[mi][dj][2 * hf + 0] *= corr;
                        oacc[mi][dj][2 * hf + 1] *= corr;
                    }
                }
            }

            // ---- O += P @ V  (P: C-frag -> A-frag via quad shuffles) ----
#pragma unroll
            for (int kc = 0; kc < 8; kc++) {
                uint32_t pa[2][4];
#pragma unroll
                for (int mi = 0; mi < 2; mi++) {
                    float e0 = __shfl_sync(0xffffffffu, sacc[mi][kc][0], src1);
                    float e1 = __shfl_sync(0xffffffffu, sacc[mi][kc][1], src1);
                    float e2 = __shfl_sync(0xffffffffu, sacc[mi][kc][2], src1);
                    float e3 = __shfl_sync(0xffffffffu, sacc[mi][kc][3], src1);
                    float f0 = __shfl_sync(0xffffffffu, sacc[mi][kc][0], src2);
                    float f1 = __shfl_sync(0xffffffffu, sacc[mi][kc][1], src2);
                    float f2 = __shfl_sync(0xffffffffu, sacc[mi][kc][2], src2);
                    float f3 = __shfl_sync(0xffffffffu, sacc[mi][kc][3], src2);
                    pa[mi][0] = f2tf32(odd ? e1 : e0);
                    pa[mi][1] = f2tf32(odd ? e3 : e2);
                    pa[mi][2] = f2tf32(odd ? f1 : f0);
                    pa[mi][3] = f2tf32(odd ? f3 : f2);
                }
#pragma unroll
                for (int dj = 0; dj < 8; dj++) {
                    uint32_t vb[2];
                    vb[0] = __float_as_uint(Vs[(kc * 8 + t4) * VSTR + dj * 8 + gid]);
                    vb[1] = __float_as_uint(Vs[(kc * 8 + t4 + 4) * VSTR + dj * 8 + gid]);
                    mma_tf32_16x8x8(oacc[0][dj], pa[0], vb);
                    mma_tf32_16x8x8(oacc[1][dj], pa[1], vb);
                }
            }
        }
        __syncthreads();
    }

    // Finalize: divide by l and write [b*S+q][h*64+d]
#pragma unroll
    for (int mi = 0; mi < 2; mi++) {
#pragma unroll
        for (int hf = 0; hf < 2; hf++) {
            float inv = 1.f / l_i[mi][hf];
            size_t row = (size_t)(b * SEQ + q0w + mi * 16 + hf * 8 + gid) * D_MODEL
                       + h * DK;
#pragma unroll
            for (int dj = 0; dj < 8; dj++) {
                float2 v = make_float2(oacc[mi][dj][2 * hf + 0] * inv,
                                       oacc[mi][dj][2 * hf + 1] * inv);
                *(float2*)&att[row + dj * 8 + 2 * t4] = v;
            }
        }
    }
}

// ---------------------------------------------------------------------------
extern "C" void kernel_launch(void* const* d_in, const int* in_sizes, int n_in,
                              void* d_out, int out_size)
{
    const float* x       = (const float*)d_in[0];
    // d_in[1] = causal mask (int32) — structure is known causal; unused
    const float* w_qkv_w = (const float*)d_in[2];
    const float* w_qkv_b = (const float*)d_in[3];
    const float* w_o_w   = (const float*)d_in[4];
    const float* w_o_b   = (const float*)d_in[5];
    float* out = (float*)d_out;

    float *qkv, *att;
    cudaGetSymbolAddress((void**)&qkv, g_qkv);
    cudaGetSymbolAddress((void**)&att, g_att);

    cudaFuncSetAttribute(gemm_mma_tf32,
                         cudaFuncAttributeMaxDynamicSharedMemorySize, GEMM_SMEM);
    cudaFuncSetAttribute(flash_attn_mma,
                         cudaFuncAttributeMaxDynamicSharedMemorySize, FA_SMEM);

    // 1) QKV projection: [4096,1024] @ [3072,1024]^T -> [4096,3072]
    dim3 g1(QKV_N / 128, MTOK / 128);
    gemm_mma_tf32<<<g1, 256, GEMM_SMEM>>>(x, w_qkv_w, w_qkv_b, qkv, MTOK, QKV_N, D_MODEL);

    // 2) Causal flash attention (tensor cores) -> [4096,1024]
    dim3 g2(SEQ / 128, NH, BATCH);
    flash_attn_mma<<<g2, 128, FA_SMEM>>>(qkv, att);

    // 3) Output projection: [4096,1024] @ [1024,1024]^T -> [4096,1024]
    dim3 g3(D_MODEL / 128, MTOK / 128);
    gemm_mma_tf32<<<g3, 256, GEMM_SMEM>>>(att, w_o_w, w_o_b, out, MTOK, D_MODEL, D_MODEL);
}